// round 12
// baseline (speedup 1.0000x reference)
#include <cuda_runtime.h>
#include <cstdint>

#define LN_EPS 1e-5f
#define D_EPS  1e-6f
#define BATCH  16
#define SEQL   2048
#define NCHUNK 32           // 32 chunks x 64 steps = 2048 (2047 real + 1 pad)

// Scratch
__device__ float g_tab[64 * 64];
__device__ float g_G[64 * 64];                     // Gram
__device__ float g_TW[64 * 64];                    // Tab @ Wr
__device__ float g_rpos[64];                       // 1/(||tab||^2 + eps)
__device__ float g_dpos[64];                       // (||tab||^2 + eps)
// per chunk 8192 floats: rows 0-63 = C, rows 64-127 = D = I - G*C
__device__ float g_CD[BATCH * NCHUNK * 8192];

// ---------------------------------------------------------------------------
__device__ __forceinline__ void cp_async16(uint32_t saddr, const void* gaddr) {
    asm volatile("cp.async.cg.shared.global [%0], [%1], 16;"
                 :: "r"(saddr), "l"(gaddr));
}
__device__ __forceinline__ void cp_commit() {
    asm volatile("cp.async.commit_group;");
}
__device__ __forceinline__ void cp_wait1() {
    asm volatile("cp.async.wait_group 1;");
}

// ---------------------------------------------------------------------------
// K1: per-token table, 16 blocks x 256 threads x 4 tokens, weights in smem.
// ---------------------------------------------------------------------------
#define TBL_SMEM_FLOATS 17184
#define TBL_SMEM_BYTES  (TBL_SMEM_FLOATS * 4)

__global__ __launch_bounds__(256) void table_kernel(
    const float* __restrict__ embed, const float* __restrict__ W1,
    const float* __restrict__ b1, const float* __restrict__ W2,
    const float* __restrict__ b2, const float* __restrict__ gamma,
    const float* __restrict__ beta)
{
    extern __shared__ float ts[];
    float* W1s  = ts;            // 8192
    float* W2s  = ts + 8192;     // 8192
    float* hsf  = ts + 16384;    // 4*64
    float* t1f  = ts + 16640;    // 4*128
    float* redf = ts + 17152;    // 4*2*2
    float* red2 = ts + 17168;    // 4*2

    const int tid = threadIdx.x;
    const int base = blockIdx.x * 4;

    for (int i = tid; i < 2048; i += 256)
        ((float4*)W1s)[i] = ((const float4*)W1)[i];
    for (int i = tid; i < 2048; i += 256)
        ((float4*)W2s)[i] = ((const float4*)W2)[i];
    {
        int tok = tid >> 6, f = tid & 63;
        hsf[tok * 64 + f] = embed[(base + tok) * 64 + f];
    }
    __syncthreads();

    #pragma unroll
    for (int k = 0; k < 2; k++) {
        int o = tid + k * 256;
        int tok = o >> 7, jj = o & 127;
        float acc = b1[jj];
        #pragma unroll
        for (int i = 0; i < 64; i++)
            acc = fmaf(hsf[tok * 64 + i], W1s[i * 128 + jj], acc);
        t1f[tok * 128 + jj] = fmaxf(acc, 0.f);
    }
    __syncthreads();

    const int tok = tid >> 6, f = tid & 63, wh = (tid >> 5) & 1;

    float acc = 0.f;
    #pragma unroll
    for (int i = 0; i < 128; i++)
        acc = fmaf(t1f[tok * 128 + i], W2s[i * 64 + f], acc);
    float x = hsf[tok * 64 + f] + acc + b2[f];

    {
        float s = x, q = x * x;
        #pragma unroll
        for (int o = 16; o > 0; o >>= 1) {
            s += __shfl_xor_sync(0xffffffffu, s, o);
            q += __shfl_xor_sync(0xffffffffu, q, o);
        }
        if ((tid & 31) == 0) {
            redf[tok * 4 + wh * 2 + 0] = s;
            redf[tok * 4 + wh * 2 + 1] = q;
        }
    }
    __syncthreads();
    float y;
    {
        float S = redf[tok * 4 + 0] + redf[tok * 4 + 2];
        float Q = redf[tok * 4 + 1] + redf[tok * 4 + 3];
        float mu = S * (1.0f / 64.0f);
        float var = Q * (1.0f / 64.0f) - mu * mu;
        y = (x - mu) * rsqrtf(var + LN_EPS) * gamma[f] + beta[f];
        g_tab[(base + tok) * 64 + f] = y;
        float z = y * y;
        #pragma unroll
        for (int o = 16; o > 0; o >>= 1)
            z += __shfl_xor_sync(0xffffffffu, z, o);
        if ((tid & 31) == 0) red2[tok * 2 + wh] = z;
    }
    __syncthreads();
    if (f == 0) {
        float d = red2[tok * 2] + red2[tok * 2 + 1] + D_EPS;
        g_dpos[base + tok] = d;
        g_rpos[base + tok] = 1.0f / d;
    }
}

// ---------------------------------------------------------------------------
// K2: G = Tab Tab^T and TW = Tab @ Wr.
// ---------------------------------------------------------------------------
__global__ __launch_bounds__(64) void gram_kernel(const float* __restrict__ Wr)
{
    __shared__ float T[64][65];
    const int a = blockIdx.x, t = threadIdx.x;
    for (int r = 0; r < 64; r++) T[r][t] = g_tab[r * 64 + t];
    __syncthreads();
    float g = 0.f, tw = 0.f;
    #pragma unroll
    for (int h = 0; h < 64; h++) {
        float av = T[a][h];
        g  = fmaf(av, T[t][h], g);
        tw = fmaf(av, Wr[h * 64 + t], tw);
    }
    g_G[a * 64 + t]  = g;
    g_TW[a * 64 + t] = tw;
}

// ---------------------------------------------------------------------------
// K3: per-chunk prep. Ainv = (I+L)^{-1}; emit token-space
//   C[a][b] = sum_{l: v_l=a} r_l * sum_{m: v_m=b} Ainv[l][m]
// into g_CD rows 0-63 of the chunk's slot.
// ---------------------------------------------------------------------------
__global__ __launch_bounds__(64) void prep_kernel(const int* __restrict__ seq)
{
    __shared__ int   vtok[64];
    __shared__ float rr[64];
    __shared__ float Lsh[64 * 65];     // L -> Ainv -> (aliased) Csh
    __shared__ float Bsh[64 * 65];

    const int blk = blockIdx.x;
    const int b = blk >> 5, c = blk & 31;
    const int t = threadIdx.x;
    const int* sq = seq + b * SEQL;

    {
        int i = c * 64 + t;                     // reversed global step index
        int v = (i < 2047) ? sq[2046 - i] : 0;  // step 2047 is pad
        vtok[t] = v;
        rr[t]   = (i < 2047) ? g_rpos[v] : 0.f;
    }
    __syncthreads();

    // L row t (strictly lower): L[t][u] = r_u * G[v_t][v_u]
    {
        const float* gr = g_G + vtok[t] * 64;
        for (int u = 0; u < t; u++)
            Lsh[t * 65 + u] = rr[u] * gr[vtok[u]];
    }
    __syncthreads();

    // forward substitution: thread t owns column t of X = (I+L)^{-1}
    float X[64];
    #pragma unroll
    for (int i2 = 0; i2 < 64; i2++) X[i2] = (i2 == t) ? 1.f : 0.f;
    #pragma unroll
    for (int u = 0; u < 63; u++) {
        float xu = X[u];
        #pragma unroll
        for (int tt = u + 1; tt < 64; tt++)
            X[tt] = fmaf(-Lsh[tt * 65 + u], xu, X[tt]);
    }
    __syncthreads();

    // Lsh <- Ainv (row r, col t)
    #pragma unroll
    for (int i2 = 0; i2 < 64; i2++) Lsh[i2 * 65 + t] = X[i2];
    __syncthreads();

    // Bsh row t: Bsh[t][b2] = sum_{m: v_m=b2} Ainv[t][m]
    for (int b2 = 0; b2 < 64; b2++) Bsh[t * 65 + b2] = 0.f;
    for (int m = 0; m < 64; m++) Bsh[t * 65 + vtok[m]] += Lsh[t * 65 + m];
    __syncthreads();       // Lsh (Ainv) dead -> reuse as Csh

    float* Csh = Lsh;
    for (int a = 0; a < 64; a++) Csh[a * 65 + t] = 0.f;
    __syncthreads();
    // column t owned exclusively
    for (int l = 0; l < 64; l++)
        Csh[vtok[l] * 65 + t] += rr[l] * Bsh[l * 65 + t];
    __syncthreads();

    {
        float4* dst = (float4*)(g_CD + (size_t)blk * 8192 + t * 64);
        const float* src = Csh + t * 65;
        #pragma unroll
        for (int j4 = 0; j4 < 16; j4++)
            dst[j4] = make_float4(src[4*j4], src[4*j4+1],
                                  src[4*j4+2], src[4*j4+3]);
    }
}

// ---------------------------------------------------------------------------
// K3b: dmat. D_c = I - G * C_c -> g_CD rows 64-127. 512 blocks x 256 thr.
// thread (r = tid>>2, q = tid&3) computes D[r][q*16 .. q*16+15].
// ---------------------------------------------------------------------------
__global__ __launch_bounds__(256) void dmat_kernel()
{
    __shared__ float Csh[64 * 64];
    __shared__ float Gsh[64 * 65];

    const int blk = blockIdx.x;
    const int tid = threadIdx.x;
    const int r = tid >> 2, q = tid & 3;
    float* CD = g_CD + (size_t)blk * 8192;

    for (int i = tid; i < 1024; i += 256)
        ((float4*)Csh)[i] = ((const float4*)CD)[i];
    for (int i = tid; i < 4096; i += 256)
        Gsh[(i >> 6) * 65 + (i & 63)] = g_G[i];
    __syncthreads();

    float4 acc0 = make_float4(0.f, 0.f, 0.f, 0.f);
    float4 acc1 = acc0, acc2 = acc0, acc3 = acc0;
    const float* gr = Gsh + r * 65;
    const float* cc = Csh + q * 16;
    #pragma unroll 8
    for (int k = 0; k < 64; k++) {
        float gk = gr[k];
        float4 c0 = *(const float4*)(cc + k * 64 + 0);
        float4 c1 = *(const float4*)(cc + k * 64 + 4);
        float4 c2 = *(const float4*)(cc + k * 64 + 8);
        float4 c3 = *(const float4*)(cc + k * 64 + 12);
        acc0.x = fmaf(gk, c0.x, acc0.x); acc0.y = fmaf(gk, c0.y, acc0.y);
        acc0.z = fmaf(gk, c0.z, acc0.z); acc0.w = fmaf(gk, c0.w, acc0.w);
        acc1.x = fmaf(gk, c1.x, acc1.x); acc1.y = fmaf(gk, c1.y, acc1.y);
        acc1.z = fmaf(gk, c1.z, acc1.z); acc1.w = fmaf(gk, c1.w, acc1.w);
        acc2.x = fmaf(gk, c2.x, acc2.x); acc2.y = fmaf(gk, c2.y, acc2.y);
        acc2.z = fmaf(gk, c2.z, acc2.z); acc2.w = fmaf(gk, c2.w, acc2.w);
        acc3.x = fmaf(gk, c3.x, acc3.x); acc3.y = fmaf(gk, c3.y, acc3.y);
        acc3.z = fmaf(gk, c3.z, acc3.z); acc3.w = fmaf(gk, c3.w, acc3.w);
    }
    // D[r][col] = delta(r,col) - acc
    float dv[16];
    dv[0]=-acc0.x; dv[1]=-acc0.y; dv[2]=-acc0.z; dv[3]=-acc0.w;
    dv[4]=-acc1.x; dv[5]=-acc1.y; dv[6]=-acc1.z; dv[7]=-acc1.w;
    dv[8]=-acc2.x; dv[9]=-acc2.y; dv[10]=-acc2.z; dv[11]=-acc2.w;
    dv[12]=-acc3.x; dv[13]=-acc3.y; dv[14]=-acc3.z; dv[15]=-acc3.w;
    int cbase = q * 16;
    if (r >= cbase && r < cbase + 16) dv[r - cbase] += 1.f;
    float4* dst = (float4*)(CD + (64 + r) * 64 + cbase);
    dst[0] = make_float4(dv[0], dv[1], dv[2], dv[3]);
    dst[1] = make_float4(dv[4], dv[5], dv[6], dv[7]);
    dst[2] = make_float4(dv[8], dv[9], dv[10], dv[11]);
    dst[3] = make_float4(dv[12], dv[13], dv[14], dv[15]);
}

// ---------------------------------------------------------------------------
// K4: chain. 1 block/batch, 256 threads = 128 rows x 2 lanes.
// [C;D] streamed by cp.async (distance 2, 3 buffers, row stride 68).
// ONE phase + ONE barrier per chunk:
//   sr<64 :  z_sr = (C w)_sr  -> zacc register (beta)
//   sr>=64:  w'_{sr-64} = (D w)_{sr-64} -> ping-pong w buffer
// Lane q reads interleaved float4 blocks (2i+q)*4: bank-conflict-free
// (17*sr + q + 2i mod 32; collision needs delta_sr = +-17 > warp range).
// ---------------------------------------------------------------------------
#define CDSTRIDE 68
#define OFF_CB   0                   // 3 * 128*68 = 26112
#define OFF_W    26112               // 2*64 ping-pong
#define OFF_BET  26240               // 64
#define OFF_HED  26304               // 64
#define SMEM_FLOATS 26368
#define SMEM_BYTES  (SMEM_FLOATS * 4)

__global__ __launch_bounds__(256) void chain_kernel(
    const int* __restrict__ seq,
    const float* __restrict__ br, const float* __restrict__ Wo,
    const float* __restrict__ bo, float* __restrict__ out)
{
    extern __shared__ float sm[];
    float* wbuf = sm + OFF_W;
    float* betash = sm + OFF_BET;
    float* hed  = sm + OFF_HED;

    const int b = blockIdx.x, tid = threadIdx.x;
    const int sr = tid >> 1, q = tid & 1;
    const int* sq = seq + b * SEQL;
    const float* CDgl = g_CD + (size_t)b * NCHUNK * 8192;

    auto issue_chunk = [&](int c) {
        float* buf = sm + OFF_CB + (c % 3) * (128 * CDSTRIDE);
        const float* src = CDgl + (size_t)c * 8192;
        #pragma unroll
        for (int k = 0; k < 8; k++) {
            int s = tid + k * 256;
            int row = s >> 4, c16 = s & 15;
            uint32_t sa = (uint32_t)__cvta_generic_to_shared(
                              buf + row * CDSTRIDE + c16 * 4);
            cp_async16(sa, src + row * 64 + c16 * 4);
        }
    };

    issue_chunk(0); cp_commit();
    issue_chunk(1); cp_commit();

    // w0 = G[:, vq]
    if (tid < 64) wbuf[tid] = g_G[tid * 64 + sq[SEQL - 1]];

    float zacc = 0.f;

    for (int c = 0; c < NCHUNK; c++) {
        cp_wait1();
        __syncthreads();           // chunk staged; prev w writes visible
        if (c + 2 < NCHUNK) issue_chunk(c + 2);
        cp_commit();

        const float* row = sm + OFF_CB + (c % 3) * (128 * CDSTRIDE)
                           + sr * CDSTRIDE;
        const float* wc = wbuf + (c & 1) * 64;

        float4 u0 = make_float4(0.f, 0.f, 0.f, 0.f);
        float4 u1 = u0;
        #pragma unroll
        for (int i = 0; i < 8; i += 2) {
            int o0 = (2 * i + q) * 4;
            int o1 = (2 * (i + 1) + q) * 4;
            float4 m0 = *(const float4*)(row + o0);
            float4 v0 = *(const float4*)(wc + o0);
            float4 m1 = *(const float4*)(row + o1);
            float4 v1 = *(const float4*)(wc + o1);
            u0.x = fmaf(m0.x, v0.x, u0.x); u0.y = fmaf(m0.y, v0.y, u0.y);
            u0.z = fmaf(m0.z, v0.z, u0.z); u0.w = fmaf(m0.w, v0.w, u0.w);
            u1.x = fmaf(m1.x, v1.x, u1.x); u1.y = fmaf(m1.y, v1.y, u1.y);
            u1.z = fmaf(m1.z, v1.z, u1.z); u1.w = fmaf(m1.w, v1.w, u1.w);
        }
        float sv = ((u0.x + u0.y) + (u0.z + u0.w))
                 + ((u1.x + u1.y) + (u1.z + u1.w));
        sv += __shfl_xor_sync(0xffffffffu, sv, 1);
        if (q == 0) {
            if (sr < 64) zacc += sv;
            else wbuf[((c + 1) & 1) * 64 + (sr - 64)] = sv;
        }
    }

    // beta[sr] = zacc * d_sr  (threads q==0, sr<64)
    if (q == 0 && sr < 64) betash[sr] = zacc * g_dpos[sr];
    __syncthreads();

    // head: out = (beta @ TW + br) @ Wo + bo
    if (tid < 64) {
        float acc = br[tid];
        #pragma unroll
        for (int a = 0; a < 64; a++)
            acc = fmaf(betash[a], g_TW[a * 64 + tid], acc);
        hed[tid] = acc;
    }
    __syncthreads();
    if (tid < 64) {
        float o = bo[tid];
        #pragma unroll
        for (int k = 0; k < 64; k++)
            o = fmaf(hed[k], Wo[k * 64 + tid], o);
        out[b * 64 + tid] = o;
    }
}

// ---------------------------------------------------------------------------
extern "C" void kernel_launch(void* const* d_in, const int* in_sizes, int n_in,
                              void* d_out, int out_size)
{
    const int*   seq   = (const int*)d_in[0];
    const float* embed = (const float*)d_in[1];
    const float* W1    = (const float*)d_in[2];
    const float* b1    = (const float*)d_in[3];
    const float* W2    = (const float*)d_in[4];
    const float* b2    = (const float*)d_in[5];
    const float* gamma = (const float*)d_in[6];
    const float* beta  = (const float*)d_in[7];
    const float* Wr    = (const float*)d_in[8];
    const float* br    = (const float*)d_in[9];
    const float* Wo    = (const float*)d_in[10];
    const float* bo    = (const float*)d_in[11];
    float* out = (float*)d_out;

    cudaFuncSetAttribute(table_kernel,
                         cudaFuncAttributeMaxDynamicSharedMemorySize,
                         TBL_SMEM_BYTES);
    cudaFuncSetAttribute(chain_kernel,
                         cudaFuncAttributeMaxDynamicSharedMemorySize,
                         SMEM_BYTES);

    table_kernel<<<16, 256, TBL_SMEM_BYTES>>>(embed, W1, b1, W2, b2, gamma, beta);
    gram_kernel<<<64, 64>>>(Wr);
    prep_kernel<<<BATCH * NCHUNK, 64>>>(seq);
    dmat_kernel<<<BATCH * NCHUNK, 256>>>();
    chain_kernel<<<BATCH, 256, SMEM_BYTES>>>(seq, br, Wo, bo, out);
}

// round 13
// speedup vs baseline: 2.5277x; 2.5277x over previous
#include <cuda_runtime.h>
#include <cstdint>

#define LN_EPS 1e-5f
#define D_EPS  1e-6f
#define BATCH  16
#define SEQL   2048
#define NSTEP  2056       // 8 warmup pads + 2047 real + 1 tail pad
#define NREC   2064

// Scratch
__device__ float g_tab[64 * 64];
__device__ float g_G[64 * 64];      // Gram
__device__ float g_TW[64 * 64];     // Tab @ Wr
__device__ float g_rpos[64];        // 1/(||tab||^2 + eps)
__device__ float g_dpos[64];        // (||tab||^2 + eps)

// ---------------------------------------------------------------------------
// K1: per-token table, 16 blocks x 256 threads x 4 tokens, weights in smem.
// ---------------------------------------------------------------------------
#define TBL_SMEM_FLOATS 17184
#define TBL_SMEM_BYTES  (TBL_SMEM_FLOATS * 4)

__global__ __launch_bounds__(256) void table_kernel(
    const float* __restrict__ embed, const float* __restrict__ W1,
    const float* __restrict__ b1, const float* __restrict__ W2,
    const float* __restrict__ b2, const float* __restrict__ gamma,
    const float* __restrict__ beta)
{
    extern __shared__ float ts[];
    float* W1s  = ts;            // 8192
    float* W2s  = ts + 8192;     // 8192
    float* hsf  = ts + 16384;    // 4*64
    float* t1f  = ts + 16640;    // 4*128
    float* redf = ts + 17152;    // 4*4
    float* red2 = ts + 17168;    // 4*2

    const int tid = threadIdx.x;
    const int base = blockIdx.x * 4;

    for (int i = tid; i < 2048; i += 256)
        ((float4*)W1s)[i] = ((const float4*)W1)[i];
    for (int i = tid; i < 2048; i += 256)
        ((float4*)W2s)[i] = ((const float4*)W2)[i];
    {
        int tok = tid >> 6, f = tid & 63;
        hsf[tok * 64 + f] = embed[(base + tok) * 64 + f];
    }
    __syncthreads();

    #pragma unroll
    for (int k = 0; k < 2; k++) {
        int o = tid + k * 256;
        int tok = o >> 7, jj = o & 127;
        float acc = b1[jj];
        #pragma unroll
        for (int i = 0; i < 64; i++)
            acc = fmaf(hsf[tok * 64 + i], W1s[i * 128 + jj], acc);
        t1f[tok * 128 + jj] = fmaxf(acc, 0.f);
    }
    __syncthreads();

    const int tok = tid >> 6, f = tid & 63, wh = (tid >> 5) & 1;

    float acc = 0.f;
    #pragma unroll
    for (int i = 0; i < 128; i++)
        acc = fmaf(t1f[tok * 128 + i], W2s[i * 64 + f], acc);
    float x = hsf[tok * 64 + f] + acc + b2[f];

    {
        float s = x, q = x * x;
        #pragma unroll
        for (int o = 16; o > 0; o >>= 1) {
            s += __shfl_xor_sync(0xffffffffu, s, o);
            q += __shfl_xor_sync(0xffffffffu, q, o);
        }
        if ((tid & 31) == 0) {
            redf[tok * 4 + wh * 2 + 0] = s;
            redf[tok * 4 + wh * 2 + 1] = q;
        }
    }
    __syncthreads();
    float y;
    {
        float S = redf[tok * 4 + 0] + redf[tok * 4 + 2];
        float Q = redf[tok * 4 + 1] + redf[tok * 4 + 3];
        float mu = S * (1.0f / 64.0f);
        float var = Q * (1.0f / 64.0f) - mu * mu;
        y = (x - mu) * rsqrtf(var + LN_EPS) * gamma[f] + beta[f];
        g_tab[(base + tok) * 64 + f] = y;
        float z = y * y;
        #pragma unroll
        for (int o = 16; o > 0; o >>= 1)
            z += __shfl_xor_sync(0xffffffffu, z, o);
        if ((tid & 31) == 0) red2[tok * 2 + wh] = z;
    }
    __syncthreads();
    if (f == 0) {
        float d = red2[tok * 2] + red2[tok * 2 + 1] + D_EPS;
        g_dpos[base + tok] = d;
        g_rpos[base + tok] = 1.0f / d;
    }
}

// ---------------------------------------------------------------------------
// K2: G = Tab Tab^T and TW = Tab @ Wr.
// ---------------------------------------------------------------------------
__global__ __launch_bounds__(64) void gram_kernel(const float* __restrict__ Wr)
{
    __shared__ float T[64][65];
    const int a = blockIdx.x, t = threadIdx.x;
    for (int r = 0; r < 64; r++) T[r][t] = g_tab[r * 64 + t];
    __syncthreads();
    float g = 0.f, tw = 0.f;
    #pragma unroll
    for (int h = 0; h < 64; h++) {
        float av = T[a][h];
        g  = fmaf(av, T[t][h], g);
        tw = fmaf(av, Wr[h * 64 + t], tw);
    }
    g_G[a * 64 + t]  = g;
    g_TW[a * 64 + t] = tw;
}

// ---------------------------------------------------------------------------
// K3: scan + head. 1 block/batch, 256 threads.
//  token-space backward scan (R3-proven math):
//    c_i = C1_i c_{i-1} + C2_i c_{i-2} + C3_i c_{i-3} + RN_i * A_i
//    A_i = w[v_i] read (shfl) 4 steps stale; w += c_i * G[:, v_i]
//    RN = -r, Ck = -r_i * G[v_i][v_{i-k}]   (all precomputed per step)
//  beta[a] = -d_a * sum_{v_i=a} c_i (post-pass over CM stream), head fused.
// ---------------------------------------------------------------------------
// smem float offsets
#define OFF_G    0        // 65*64 = 4160 (row 64 = zeros, pad token)
#define OFF_RA   4160     // 2064*4 float4 {C1,C2,C3,RN}
#define OFF_IO   12416    // 2064*4 int4 {idx, odd, v*64, v}
#define OFF_VS   20672    // 2064 int v
#define OFF_CM   22736    // 2064 float c
#define OFF_PART 24800    // 256 (aliased as rns[65] during Phase B)
#define OFF_BET  25056    // 64
#define OFF_HED  25120    // 64
#define SCN_SMEM_FLOATS 25184
#define SCN_SMEM_BYTES  (SCN_SMEM_FLOATS * 4)

__global__ __launch_bounds__(256) void scan_kernel(
    const int* __restrict__ seq,
    const float* __restrict__ br, const float* __restrict__ Wo,
    const float* __restrict__ bo, float* __restrict__ out)
{
    extern __shared__ float sm[];
    float*  Gsh = sm + OFF_G;
    float4* RAp = (float4*)(sm + OFF_RA);
    int4*   IOp = (int4*)(sm + OFF_IO);
    int*    VSp = (int*)(sm + OFF_VS);
    float*  CMp = sm + OFF_CM;
    float*  part = sm + OFF_PART;
    float*  rns  = sm + OFF_PART;      // alias, used only in Phase B
    float*  betash = sm + OFF_BET;
    float*  hed  = sm + OFF_HED;

    const int b = blockIdx.x, tid = threadIdx.x;
    const int* sq = seq + b * SEQL;

    // ---- Phase A: stage G (65 rows, row 64 zero), token stream, rns ----
    for (int e = tid; e < 4160; e += 256)
        Gsh[e] = (e < 4096) ? g_G[e] : 0.f;
    for (int i = tid; i < NREC; i += 256)
        VSp[i] = (i >= 8 && i < 2055) ? sq[2054 - i] : 64;
    if (tid < 65) rns[tid] = (tid < 64) ? -g_rpos[tid] : 0.f;
    __syncthreads();

    // ---- Phase B: per-step records ----
    for (int i = tid; i < NREC; i += 256) {
        int v = VSp[i];
        float rn = rns[v];
        const float* gr = Gsh + v * 64;
        float c1 = (i >= 1) ? rn * gr[VSp[i - 1] & 63] : 0.f;
        float c2 = (i >= 2) ? rn * gr[VSp[i - 2] & 63] : 0.f;
        float c3 = (i >= 3) ? rn * gr[VSp[i - 3] & 63] : 0.f;
        RAp[i] = make_float4(c1, c2, c3, rn);
        IOp[i] = make_int4(v >> 1, v & 1, v * 64, v);
    }
    __syncthreads();

    // ---- Phase C: warp 0 scalar scan ----
    if (tid < 32) {
        const int l = tid;
        const int e0 = 2 * l;
        const int vq = sq[SEQL - 1];
        float w0 = Gsh[e0 * 64 + vq];
        float w1 = Gsh[(e0 + 1) * 64 + vq];

        float4 rotA[8]; int4 rotIO[8]; float2 rotGP[8];
        float Abuf[4] = {0.f, 0.f, 0.f, 0.f};
        float T2b[4]  = {0.f, 0.f, 0.f, 0.f};
        float T1b[4]  = {0.f, 0.f, 0.f, 0.f};
        #pragma unroll
        for (int j2 = 0; j2 < 8; j2++) {
            rotA[j2] = make_float4(0.f, 0.f, 0.f, 0.f);
            rotIO[j2] = make_int4(0, 0, 64 * 64, 64);
            rotGP[j2] = make_float2(0.f, 0.f);
        }
        #pragma unroll
        for (int j2 = 0; j2 < 6; j2++) {
            rotA[j2] = RAp[j2];
            rotIO[j2] = IOp[j2];
        }
        #pragma unroll
        for (int j2 = 0; j2 < 3; j2++)
            rotGP[j2] = *(const float2*)(Gsh + rotIO[j2].z + e0);

        float cm = 0.f;
        const bool lead = (l == 0);

        #pragma unroll 8
        for (int i = 0; i < NSTEP; i++) {
            const int s0 = i & 7, s3r = (i + 3) & 7;
            const int s4r = (i + 4) & 7, s6 = (i + 6) & 7;
            cm = fmaf(cm, rotA[s0].x, T1b[i & 3]);
            if (lead) CMp[i] = cm;
            float2 gp = rotGP[s0];
            w0 = fmaf(cm, gp.x, w0);
            w1 = fmaf(cm, gp.y, w1);
            int4 io4 = rotIO[s4r];
            float ws = io4.y ? w1 : w0;
            Abuf[i & 3] = __shfl_sync(0xffffffffu, ws, io4.x);
            float4 a3 = rotA[s3r];
            float P = a3.w * Abuf[(i + 3) & 3];
            T2b[(i + 3) & 3] = fmaf(cm, a3.z, P);
            T1b[(i + 2) & 3] = fmaf(cm, rotA[(i + 2) & 7].y, T2b[(i + 2) & 3]);
            rotGP[s3r] = *(const float2*)(Gsh + rotIO[s3r].z + e0);
            rotA[s6] = RAp[i + 6];
            rotIO[s6] = IOp[i + 6];
        }
    }
    __syncthreads();

    // ---- Phase D: beta gather + head ----
    {
        const int a = tid & 63, qd = tid >> 6;
        float p = 0.f;
        for (int i = qd * 4; i < NSTEP; i += 16) {
            float4 c4 = *(const float4*)&CMp[i];
            int4  v4 = *(const int4*)&VSp[i];
            if (v4.x == a) p += c4.x;
            if (v4.y == a) p += c4.y;
            if (v4.z == a) p += c4.z;
            if (v4.w == a) p += c4.w;
        }
        __syncthreads();           // rns alias dead; safe to overwrite part
        part[qd * 64 + a] = p;
    }
    __syncthreads();
    if (tid < 64) {
        float s = part[tid] + part[64 + tid] + part[128 + tid]
                + part[192 + tid];
        betash[tid] = -s * g_dpos[tid];
    }
    __syncthreads();
    if (tid < 64) {
        float acc = br[tid];
        #pragma unroll
        for (int a = 0; a < 64; a++)
            acc = fmaf(betash[a], g_TW[a * 64 + tid], acc);
        hed[tid] = acc;
    }
    __syncthreads();
    if (tid < 64) {
        float o = bo[tid];
        #pragma unroll
        for (int k = 0; k < 64; k++)
            o = fmaf(hed[k], Wo[k * 64 + tid], o);
        out[b * 64 + tid] = o;
    }
}

// ---------------------------------------------------------------------------
extern "C" void kernel_launch(void* const* d_in, const int* in_sizes, int n_in,
                              void* d_out, int out_size)
{
    const int*   seq   = (const int*)d_in[0];
    const float* embed = (const float*)d_in[1];
    const float* W1    = (const float*)d_in[2];
    const float* b1    = (const float*)d_in[3];
    const float* W2    = (const float*)d_in[4];
    const float* b2    = (const float*)d_in[5];
    const float* gamma = (const float*)d_in[6];
    const float* beta  = (const float*)d_in[7];
    const float* Wr    = (const float*)d_in[8];
    const float* br    = (const float*)d_in[9];
    const float* Wo    = (const float*)d_in[10];
    const float* bo    = (const float*)d_in[11];
    float* out = (float*)d_out;

    cudaFuncSetAttribute(table_kernel,
                         cudaFuncAttributeMaxDynamicSharedMemorySize,
                         TBL_SMEM_BYTES);
    cudaFuncSetAttribute(scan_kernel,
                         cudaFuncAttributeMaxDynamicSharedMemorySize,
                         SCN_SMEM_BYTES);

    table_kernel<<<16, 256, TBL_SMEM_BYTES>>>(embed, W1, b1, W2, b2, gamma, beta);
    gram_kernel<<<64, 64>>>(Wr);
    scan_kernel<<<BATCH, 256, SCN_SMEM_BYTES>>>(seq, br, Wo, bo, out);
}

// round 14
// speedup vs baseline: 2.5358x; 1.0032x over previous
#include <cuda_runtime.h>
#include <cstdint>

#define LN_EPS 1e-5f
#define D_EPS  1e-6f
#define BATCH  16
#define SEQL   2048
#define NCHUNK 32           // 32 chunks x 64 steps = 2048 (2047 real + 1 pad)

// Scratch
__device__ float g_tab[64 * 64];
__device__ float g_G[64 * 64];                     // Gram
__device__ float g_TW[64 * 64];                    // Tab @ Wr
__device__ float g_rpos[64];                       // 1/(||tab||^2 + eps)
__device__ float g_dpos[64];                       // (||tab||^2 + eps)
// per chunk: token-space C (64x64): z = C w drives both beta and w-update
__device__ float g_C[BATCH * NCHUNK * 4096];

// ---------------------------------------------------------------------------
__device__ __forceinline__ void cp_async16(uint32_t saddr, const void* gaddr) {
    asm volatile("cp.async.cg.shared.global [%0], [%1], 16;"
                 :: "r"(saddr), "l"(gaddr));
}
__device__ __forceinline__ void cp_commit() {
    asm volatile("cp.async.commit_group;");
}
__device__ __forceinline__ void cp_wait4() {
    asm volatile("cp.async.wait_group 4;");
}

// ---------------------------------------------------------------------------
// K1: per-token table (R3-proven 64-block version): tab[a] = LN(e_a+MLP(e_a))
// ---------------------------------------------------------------------------
__global__ __launch_bounds__(128) void table_kernel(
    const float* __restrict__ embed, const float* __restrict__ W1,
    const float* __restrict__ b1, const float* __restrict__ W2,
    const float* __restrict__ b2, const float* __restrict__ gamma,
    const float* __restrict__ beta)
{
    __shared__ float hs[64];
    __shared__ float t1s[128];
    __shared__ float xh[2][64];
    __shared__ float red[2][2];

    const int a = blockIdx.x, tid = threadIdx.x;
    if (tid < 64) hs[tid] = embed[a * 64 + tid];
    __syncthreads();

    float acc = b1[tid];
    #pragma unroll
    for (int i = 0; i < 64; i++) acc = fmaf(hs[i], W1[i * 128 + tid], acc);
    t1s[tid] = fmaxf(acc, 0.f);
    __syncthreads();

    {
        int j = tid & 63, half = tid >> 6;
        float a2 = 0.f;
        #pragma unroll
        for (int ii = 0; ii < 64; ii++) {
            int i = half * 64 + ii;
            a2 = fmaf(t1s[i], W2[i * 64 + j], a2);
        }
        xh[half][j] = a2;
    }
    __syncthreads();

    float x = 0.f, y = 0.f;
    if (tid < 64) {
        x = hs[tid] + xh[0][tid] + xh[1][tid] + b2[tid];
        float s = x, q = x * x;
        #pragma unroll
        for (int o = 16; o > 0; o >>= 1) {
            s += __shfl_xor_sync(0xffffffffu, s, o);
            q += __shfl_xor_sync(0xffffffffu, q, o);
        }
        if ((tid & 31) == 0) { red[tid >> 5][0] = s; red[tid >> 5][1] = q; }
    }
    __syncthreads();
    if (tid < 64) {
        float S = red[0][0] + red[1][0];
        float Q = red[0][1] + red[1][1];
        float mu = S * (1.0f / 64.0f);
        float var = Q * (1.0f / 64.0f) - mu * mu;
        y = (x - mu) * rsqrtf(var + LN_EPS) * gamma[tid] + beta[tid];
        g_tab[a * 64 + tid] = y;
        float z = y * y;
        #pragma unroll
        for (int o = 16; o > 0; o >>= 1) z += __shfl_xor_sync(0xffffffffu, z, o);
        if ((tid & 31) == 0) red[tid >> 5][0] = z;
    }
    __syncthreads();
    if (tid == 0) {
        float d = red[0][0] + red[1][0] + D_EPS;
        g_dpos[a] = d;
        g_rpos[a] = 1.0f / d;
    }
}

// ---------------------------------------------------------------------------
// K2: G = Tab Tab^T and TW = Tab @ Wr.
// ---------------------------------------------------------------------------
__global__ __launch_bounds__(64) void gram_kernel(const float* __restrict__ Wr)
{
    __shared__ float T[64][65];
    const int a = blockIdx.x, t = threadIdx.x;
    for (int r = 0; r < 64; r++) T[r][t] = g_tab[r * 64 + t];
    __syncthreads();
    float g = 0.f, tw = 0.f;
    #pragma unroll
    for (int h = 0; h < 64; h++) {
        float av = T[a][h];
        g  = fmaf(av, T[t][h], g);
        tw = fmaf(av, Wr[h * 64 + t], tw);
    }
    g_G[a * 64 + t]  = g;
    g_TW[a * 64 + t] = tw;
}

// ---------------------------------------------------------------------------
// K3: per-chunk prep (R11-proven). Ainv = (I+L)^{-1}; emit token-space
//   C[a][b] = sum_{l: v_l=a} r_l * sum_{m: v_m=b} Ainv[l][m]
// ---------------------------------------------------------------------------
__global__ __launch_bounds__(64) void prep_kernel(const int* __restrict__ seq)
{
    __shared__ int   vtok[64];
    __shared__ float rr[64];
    __shared__ float Lsh[64 * 65];     // L -> Ainv -> (aliased) Csh
    __shared__ float Bsh[64 * 65];

    const int blk = blockIdx.x;
    const int b = blk >> 5, c = blk & 31;
    const int t = threadIdx.x;
    const int* sq = seq + b * SEQL;

    {
        int i = c * 64 + t;                     // reversed global step index
        int v = (i < 2047) ? sq[2046 - i] : 0;  // step 2047 is pad
        vtok[t] = v;
        rr[t]   = (i < 2047) ? g_rpos[v] : 0.f;
    }
    __syncthreads();

    // L row t (strictly lower): L[t][u] = r_u * G[v_t][v_u]
    {
        const float* gr = g_G + vtok[t] * 64;
        for (int u = 0; u < t; u++)
            Lsh[t * 65 + u] = rr[u] * gr[vtok[u]];
    }
    __syncthreads();

    // forward substitution: thread t owns column t of X = (I+L)^{-1}
    float X[64];
    #pragma unroll
    for (int i2 = 0; i2 < 64; i2++) X[i2] = (i2 == t) ? 1.f : 0.f;
    #pragma unroll
    for (int u = 0; u < 63; u++) {
        float xu = X[u];
        #pragma unroll
        for (int tt = u + 1; tt < 64; tt++)
            X[tt] = fmaf(-Lsh[tt * 65 + u], xu, X[tt]);
    }
    __syncthreads();

    // Lsh <- Ainv (row r, col t)
    #pragma unroll
    for (int i2 = 0; i2 < 64; i2++) Lsh[i2 * 65 + t] = X[i2];
    __syncthreads();

    // Bsh row t: Bsh[t][b2] = sum_{m: v_m=b2} Ainv[t][m]
    for (int b2 = 0; b2 < 64; b2++) Bsh[t * 65 + b2] = 0.f;
    for (int m = 0; m < 64; m++) Bsh[t * 65 + vtok[m]] += Lsh[t * 65 + m];
    __syncthreads();       // Lsh (Ainv) dead -> reuse as Csh

    float* Csh = Lsh;
    for (int a = 0; a < 64; a++) Csh[a * 65 + t] = 0.f;
    __syncthreads();
    // column t owned exclusively
    for (int l = 0; l < 64; l++)
        Csh[vtok[l] * 65 + t] += rr[l] * Bsh[l * 65 + t];
    __syncthreads();

    {
        float4* dst = (float4*)(g_C + (size_t)blk * 4096 + t * 64);
        const float* src = Csh + t * 65;
        #pragma unroll
        for (int j4 = 0; j4 < 16; j4++)
            dst[j4] = make_float4(src[4*j4], src[4*j4+1],
                                  src[4*j4+2], src[4*j4+3]);
    }
}

// ---------------------------------------------------------------------------
// K4: chain. 1 block/batch, 256 threads = 64 rows x 4 lanes.
// C streamed by cp.async at DISTANCE 5 (6 smem buffers, stride-68 rows);
// G resident. Per chunk (2 barriers): z = C w (zacc += z); w -= G z.
// Post: beta = d .* zacc; head -> out.
// ---------------------------------------------------------------------------
#define ASTRIDE  68
#define NBUF     6
#define OFF_CB   0                  // 6*64*68 = 26112
#define OFF_GS   26112              // 4352
#define OFF_W    30464              // 64
#define OFF_Z    30528              // 64
#define OFF_BET  30592              // 64
#define OFF_HED  30656              // 64
#define SMEM_FLOATS 30720
#define SMEM_BYTES  (SMEM_FLOATS * 4)

__global__ __launch_bounds__(256) void chain_kernel(
    const int* __restrict__ seq,
    const float* __restrict__ br, const float* __restrict__ Wo,
    const float* __restrict__ bo, float* __restrict__ out)
{
    extern __shared__ float sm[];
    float* Gs   = sm + OFF_GS;
    float* wsh  = sm + OFF_W;
    float* zsh  = sm + OFF_Z;
    float* betash = sm + OFF_BET;
    float* hed  = sm + OFF_HED;

    const int b = blockIdx.x, tid = threadIdx.x;
    const int j = tid >> 2, q = tid & 3;
    const int* sq = seq + b * SEQL;
    const float* Cgl = g_C + (size_t)b * NCHUNK * 4096;

    auto issue_chunk = [&](int c) {
        float* buf = sm + OFF_CB + (c % NBUF) * (64 * ASTRIDE);
        const float* src = Cgl + (size_t)c * 4096;
        #pragma unroll
        for (int k = 0; k < 4; k++) {
            int s = tid + k * 256;
            int row = s >> 4, c16 = s & 15;
            uint32_t sa = (uint32_t)__cvta_generic_to_shared(
                              buf + row * ASTRIDE + c16 * 4);
            cp_async16(sa, src + row * 64 + c16 * 4);
        }
    };

    // prologue: fill pipeline to depth 5
    #pragma unroll
    for (int c0 = 0; c0 < 5; c0++) { issue_chunk(c0); cp_commit(); }

    // stage G (stride 68) + w0 (overlaps in-flight cp.async groups)
    for (int idx = tid; idx < 4096; idx += 256)
        Gs[(idx >> 6) * ASTRIDE + (idx & 63)] = g_G[idx];
    if (tid < 64) wsh[tid] = g_G[tid * 64 + sq[SEQL - 1]];

    float zacc = 0.f;     // meaningful on q==0 lanes (row j)

    for (int c = 0; c < NCHUNK; c++) {
        cp_wait4();               // group for chunk c complete
        __syncthreads();          // staged + prev w-update visible
        if (c + 5 < NCHUNK) issue_chunk(c + 5);
        cp_commit();              // always commit (uniform group counting)

        const float* buf = sm + OFF_CB + (c % NBUF) * (64 * ASTRIDE);

        // --- phase 1: z_j = (C w)_j ---
        {
            const float* ab = buf + j * ASTRIDE + q * 16;
            const float4* pv = (const float4*)(wsh + q * 16);
            float4 a0 = *(const float4*)(ab + 0);
            float4 a1 = *(const float4*)(ab + 4);
            float4 a2 = *(const float4*)(ab + 8);
            float4 a3 = *(const float4*)(ab + 12);
            float4 p0 = pv[0], p1 = pv[1], p2 = pv[2], p3 = pv[3];
            float u0 = fmaf(a0.x, p0.x, a0.y * p0.y);
            u0 = fmaf(a0.z, p0.z, u0); u0 = fmaf(a0.w, p0.w, u0);
            float u1 = fmaf(a1.x, p1.x, a1.y * p1.y);
            u1 = fmaf(a1.z, p1.z, u1); u1 = fmaf(a1.w, p1.w, u1);
            float u2 = fmaf(a2.x, p2.x, a2.y * p2.y);
            u2 = fmaf(a2.z, p2.z, u2); u2 = fmaf(a2.w, p2.w, u2);
            float u3 = fmaf(a3.x, p3.x, a3.y * p3.y);
            u3 = fmaf(a3.z, p3.z, u3); u3 = fmaf(a3.w, p3.w, u3);
            float sv = (u0 + u1) + (u2 + u3);
            sv += __shfl_xor_sync(0xffffffffu, sv, 1);
            sv += __shfl_xor_sync(0xffffffffu, sv, 2);
            if (q == 0) { zsh[j] = sv; zacc += sv; }
        }
        __syncthreads();

        // --- phase 2: w_j -= (G z)_j ---
        {
            const float* gr = Gs + j * ASTRIDE + q * 16;
            const float4* zv = (const float4*)(zsh + q * 16);
            float4 g0 = *(const float4*)(gr + 0);
            float4 g1 = *(const float4*)(gr + 4);
            float4 g2 = *(const float4*)(gr + 8);
            float4 g3 = *(const float4*)(gr + 12);
            float4 z0 = zv[0], z1 = zv[1], z2 = zv[2], z3 = zv[3];
            float u0 = fmaf(g0.x, z0.x, g0.y * z0.y);
            u0 = fmaf(g0.z, z0.z, u0); u0 = fmaf(g0.w, z0.w, u0);
            float u1 = fmaf(g1.x, z1.x, g1.y * z1.y);
            u1 = fmaf(g1.z, z1.z, u1); u1 = fmaf(g1.w, z1.w, u1);
            float u2 = fmaf(g2.x, z2.x, g2.y * z2.y);
            u2 = fmaf(g2.z, z2.z, u2); u2 = fmaf(g2.w, z2.w, u2);
            float u3 = fmaf(g3.x, z3.x, g3.y * z3.y);
            u3 = fmaf(g3.z, z3.z, u3); u3 = fmaf(g3.w, z3.w, u3);
            float du = (u0 + u1) + (u2 + u3);
            du += __shfl_xor_sync(0xffffffffu, du, 1);
            du += __shfl_xor_sync(0xffffffffu, du, 2);
            if (q == 0) wsh[j] -= du;
        }
    }

    // beta[j] = zacc * d_j
    if (q == 0) betash[j] = zacc * g_dpos[j];
    __syncthreads();

    // head: out = (beta @ TW + br) @ Wo + bo
    if (tid < 64) {
        float acc = br[tid];
        #pragma unroll
        for (int a = 0; a < 64; a++)
            acc = fmaf(betash[a], g_TW[a * 64 + tid], acc);
        hed[tid] = acc;
    }
    __syncthreads();
    if (tid < 64) {
        float o = bo[tid];
        #pragma unroll
        for (int k = 0; k < 64; k++)
            o = fmaf(hed[k], Wo[k * 64 + tid], o);
        out[b * 64 + tid] = o;
    }
}

// ---------------------------------------------------------------------------
extern "C" void kernel_launch(void* const* d_in, const int* in_sizes, int n_in,
                              void* d_out, int out_size)
{
    const int*   seq   = (const int*)d_in[0];
    const float* embed = (const float*)d_in[1];
    const float* W1    = (const float*)d_in[2];
    const float* b1    = (const float*)d_in[3];
    const float* W2    = (const float*)d_in[4];
    const float* b2    = (const float*)d_in[5];
    const float* gamma = (const float*)d_in[6];
    const float* beta  = (const float*)d_in[7];
    const float* Wr    = (const float*)d_in[8];
    const float* br    = (const float*)d_in[9];
    const float* Wo    = (const float*)d_in[10];
    const float* bo    = (const float*)d_in[11];
    float* out = (float*)d_out;

    cudaFuncSetAttribute(chain_kernel,
                         cudaFuncAttributeMaxDynamicSharedMemorySize,
                         SMEM_BYTES);

    table_kernel<<<64, 128>>>(embed, W1, b1, W2, b2, gamma, beta);
    gram_kernel<<<64, 64>>>(Wr);
    prep_kernel<<<BATCH * NCHUNK, 64>>>(seq);
    chain_kernel<<<BATCH, 256, SMEM_BYTES>>>(seq, br, Wo, bo, out);
}